// round 2
// baseline (speedup 1.0000x reference)
#include <cuda_runtime.h>
#include <math.h>

#define BB     64
#define NCH    129
#define NT     200
#define DM     256
#define DSTATE 16
#define HD     32
#define NL     4
#define DI     512
#define NH     16
#define CONVD  544
#define DPROJ  1072
#define TOK    (BB*NT)   // 12800
#define KPAD   136       // 129 padded to mult of 8

// ---------------- scratch (device globals; no allocation allowed) ----------
__device__ float g_xsr[TOK*KPAD];      // encoder conv output, (bt, c) K-padded
__device__ float g_mixw[DM*KPAD];      // mixer_w padded to K=136
__device__ float g_biasenc[DM];        // mixer_b + emb.mean(0)
__device__ float g_h[TOK*DM];          // residual stream
__device__ float g_zx[TOK*DPROJ];      // in_proj output
__device__ float g_xbc[TOK*CONVD];     // conv+silu output
__device__ float g_dt[TOK*NH];
__device__ float g_dA[TOK*NH];
__device__ float g_y[TOK*DI];          // ssm output / gated-normed
__device__ float g_o[TOK*DM];          // out_proj output
__device__ float g_pool[BB*DM];

// ---------------- helpers --------------------------------------------------
__device__ __forceinline__ float blockReduceSum(float v, volatile float* sh) {
    __syncthreads();
    int lane = threadIdx.x & 31, wid = threadIdx.x >> 5;
#pragma unroll
    for (int o = 16; o > 0; o >>= 1) v += __shfl_xor_sync(0xffffffffu, v, o);
    if (lane == 0) sh[wid] = v;
    __syncthreads();
    float tot = 0.f;
    int nw = blockDim.x >> 5;
    for (int i = 0; i < nw; i++) tot += sh[i];
    return tot;
}

__device__ __forceinline__ float siluf(float x) { return x / (1.f + expf(-x)); }

// ---------------- SGEMM: C[m,n] = sum_k A[m,k]*W[n,k] (+bias[n]) ----------
// A: M x K row-major, W: N x K row-major, C: M x N dense. M % 128 == 0, K % 8 == 0.
__global__ void sgemm_nt(const float* __restrict__ A, const float* __restrict__ W,
                         const float* __restrict__ bias, float* __restrict__ C,
                         int M, int N, int K) {
    __shared__ float As[8][128];
    __shared__ float Ws[8][128];
    const int bm = blockIdx.y * 128, bn = blockIdx.x * 128;
    const int tid = threadIdx.x;               // 256 threads
    const int lrow = tid >> 1, lk4 = (tid & 1) << 2;
    const int tx = tid & 15, ty = tid >> 4;

    float acc[8][8];
#pragma unroll
    for (int i = 0; i < 8; i++)
#pragma unroll
        for (int j = 0; j < 8; j++) acc[i][j] = 0.f;

    const float* Aptr = A + (size_t)(bm + lrow) * K + lk4;
    const float* Wptr = W + (size_t)(bn + lrow) * K + lk4;
    const bool wvalid = (bn + lrow) < N;

    for (int k0 = 0; k0 < K; k0 += 8) {
        float4 a4 = *(const float4*)(Aptr + k0);
        float4 w4 = wvalid ? *(const float4*)(Wptr + k0) : make_float4(0.f, 0.f, 0.f, 0.f);
        As[lk4 + 0][lrow] = a4.x; As[lk4 + 1][lrow] = a4.y;
        As[lk4 + 2][lrow] = a4.z; As[lk4 + 3][lrow] = a4.w;
        Ws[lk4 + 0][lrow] = w4.x; Ws[lk4 + 1][lrow] = w4.y;
        Ws[lk4 + 2][lrow] = w4.z; Ws[lk4 + 3][lrow] = w4.w;
        __syncthreads();
#pragma unroll
        for (int kk = 0; kk < 8; kk++) {
            float a[8], bv[8];
#pragma unroll
            for (int i = 0; i < 8; i++) a[i] = As[kk][ty * 8 + i];
#pragma unroll
            for (int j = 0; j < 8; j++) bv[j] = Ws[kk][tx * 8 + j];
#pragma unroll
            for (int i = 0; i < 8; i++)
#pragma unroll
                for (int j = 0; j < 8; j++) acc[i][j] = fmaf(a[i], bv[j], acc[i][j]);
        }
        __syncthreads();
    }

    float bj[8];
#pragma unroll
    for (int j = 0; j < 8; j++) {
        int n = bn + tx * 8 + j;
        bj[j] = (bias != nullptr && n < N) ? bias[n] : 0.f;
    }
#pragma unroll
    for (int i = 0; i < 8; i++) {
        int m = bm + ty * 8 + i;
#pragma unroll
        for (int j = 0; j < 8; j++) {
            int n = bn + tx * 8 + j;
            if (n < N) C[(size_t)m * N + n] = acc[i][j] + bj[j];
        }
    }
}

// ---------------- encoder --------------------------------------------------
// depthwise conv(K=3, pad 1) over time; output transposed to (bt, c) with zero K-pad
__global__ void k_sconv(const float* __restrict__ x, const float* __restrict__ w,
                        const float* __restrict__ bias) {
    int c = blockIdx.x, b = blockIdx.y, t = threadIdx.x; // c in [0,136)
    float v = 0.f;
    if (c < NCH) {
        const float* xr = x + (size_t)(b * NCH + c) * NT;
        float w0 = w[c * 3], w1 = w[c * 3 + 1], w2 = w[c * 3 + 2];
        float xm = (t > 0) ? xr[t - 1] : 0.f;
        float x0 = xr[t];
        float xp = (t < NT - 1) ? xr[t + 1] : 0.f;
        v = xm * w0 + x0 * w1 + xp * w2 + bias[c];
    }
    g_xsr[(size_t)(b * NT + t) * KPAD + c] = v;
}

__global__ void k_mixprep(const float* __restrict__ mw) {
    int idx = blockIdx.x * blockDim.x + threadIdx.x;
    if (idx >= DM * KPAD) return;
    int d = idx / KPAD, k = idx % KPAD;
    g_mixw[idx] = (k < NCH) ? mw[d * NCH + k] : 0.f;
}

__global__ void k_biasenc(const float* __restrict__ emb, const float* __restrict__ mb) {
    int d = threadIdx.x;
    float s = 0.f;
    for (int c = 0; c < NCH; c++) s += emb[c * DM + d];
    g_biasenc[d] = mb[d] + s * (1.f / NCH);
}

// ---------------- layernorm (row = 256); res may be null; in-place safe ----
__global__ void k_ln(const float* __restrict__ in, const float* __restrict__ res,
                     const float* __restrict__ w, const float* __restrict__ b,
                     float* __restrict__ out) {
    __shared__ float sh[8];
    int row = blockIdx.x, tid = threadIdx.x;
    float v = in[(size_t)row * DM + tid];
    if (res != nullptr) v += res[(size_t)row * DM + tid];
    float mean = blockReduceSum(v, sh) * (1.f / DM);
    float d = v - mean;
    float var = blockReduceSum(d * d, sh) * (1.f / DM);
    out[(size_t)row * DM + tid] = d * rsqrtf(var + 1e-5f) * w[tid] + b[tid];
}

// ---------------- per-layer pieces -----------------------------------------
__global__ void k_dt(const float* __restrict__ dtb, const float* __restrict__ alog) {
    int idx = blockIdx.x * blockDim.x + threadIdx.x;
    if (idx >= TOK * NH) return;
    int h = idx & 15, bt = idx >> 4;
    float raw = g_zx[(size_t)bt * DPROJ + DI + CONVD + h] + dtb[h];
    float d = raw > 20.f ? raw : log1pf(expf(raw));
    g_dt[idx] = d;
    g_dA[idx] = expf(-d * expf(alog[h]));
}

// causal depthwise conv K=4 (pad 3 left) + silu on xBC slice of zxbcdt
__global__ void k_conv(const float* __restrict__ cw, const float* __restrict__ cb) {
    int idx = blockIdx.x * blockDim.x + threadIdx.x;
    if (idx >= TOK * CONVD) return;
    int c = idx % CONVD;
    int bt = idx / CONVD;
    int t = bt % NT, b = bt / NT;
    float acc = cb[c];
    const float* wr = cw + c * 4;
#pragma unroll
    for (int k = 0; k < 4; k++) {
        int tt = t - 3 + k;
        if (tt >= 0) acc = fmaf(g_zx[(size_t)(b * NT + tt) * DPROJ + DI + c], wr[k], acc);
    }
    g_xbc[idx] = siluf(acc);
}

// sequential SSM scan; block = (b, h); thread = (p, n); shuffle-reduce over n
__global__ void k_scan(const float* __restrict__ Dsk) {
    int b = blockIdx.x, h = blockIdx.y;
    int tid = threadIdx.x;                  // 512
    int p = tid >> 4, n = tid & 15;
    float Dh = Dsk[h];
    float state = 0.f;
    int base = b * NT;
    for (int t = 0; t < NT; t++) {
        int bt = base + t;
        float dAt = g_dA[bt * NH + h];
        float dtt = g_dt[bt * NH + h];
        const float* row = g_xbc + (size_t)bt * CONVD;
        float xp = row[h * HD + p];
        float Bn = row[DI + n];
        float Cn = row[DI + DSTATE + n];
        state = fmaf(dAt, state, dtt * xp * Bn);
        float part = state * Cn;
        part += __shfl_xor_sync(0xffffffffu, part, 1);
        part += __shfl_xor_sync(0xffffffffu, part, 2);
        part += __shfl_xor_sync(0xffffffffu, part, 4);
        part += __shfl_xor_sync(0xffffffffu, part, 8);
        if (n == 0) g_y[(size_t)bt * DI + h * HD + p] = part + xp * Dh;
    }
}

// gated RMSNorm over 512, in place on g_y; gate z read from g_zx
__global__ void k_rms(const float* __restrict__ nw) {
    __shared__ float sh[8];
    int row = blockIdx.x, tid = threadIdx.x; // 256
    float z0 = g_zx[(size_t)row * DPROJ + tid];
    float z1 = g_zx[(size_t)row * DPROJ + 256 + tid];
    float y0 = g_y[(size_t)row * DI + tid];
    float y1 = g_y[(size_t)row * DI + 256 + tid];
    y0 *= siluf(z0);
    y1 *= siluf(z1);
    float ss = blockReduceSum(y0 * y0 + y1 * y1, sh);
    float sc = rsqrtf(ss * (1.f / DI) + 1e-5f);
    g_y[(size_t)row * DI + tid]       = y0 * sc * nw[tid];
    g_y[(size_t)row * DI + 256 + tid] = y1 * sc * nw[256 + tid];
}

// ---------------- head -----------------------------------------------------
__global__ void k_pool() {
    int b = blockIdx.x, d = threadIdx.x;
    float s = 0.f;
    for (int t = 0; t < NT; t++) s += g_h[(size_t)(b * NT + t) * DM + d];
    g_pool[b * DM + d] = s * (1.f / NT);
}

__global__ void k_head(const float* __restrict__ w1, const float* __restrict__ b1,
                       const float* __restrict__ w2, const float* __restrict__ b2,
                       float* __restrict__ out) {
    __shared__ float sp[DM];
    __shared__ float sh[4];
    int b = blockIdx.x, j = threadIdx.x;    // 128
    sp[j] = g_pool[b * DM + j];
    sp[j + 128] = g_pool[b * DM + 128 + j];
    __syncthreads();
    float acc = b1[j];
    const float* wr = w1 + j * DM;
#pragma unroll 8
    for (int k = 0; k < DM; k++) acc = fmaf(sp[k], wr[k], acc);
    float r = fmaxf(acc, 0.f) * w2[j];
#pragma unroll
    for (int o = 16; o > 0; o >>= 1) r += __shfl_xor_sync(0xffffffffu, r, o);
    int lane = j & 31, wid = j >> 5;
    if (lane == 0) sh[wid] = r;
    __syncthreads();
    if (j == 0) out[b] = sh[0] + sh[1] + sh[2] + sh[3] + b2[0];
}

// ---------------- launch ----------------------------------------------------
extern "C" void kernel_launch(void* const* d_in, const int* in_sizes, int n_in,
                              void* d_out, int out_size) {
    const float* x         = (const float*)d_in[0];
    const float* emb       = (const float*)d_in[1];
    const float* sconv_w   = (const float*)d_in[2];
    const float* sconv_b   = (const float*)d_in[3];
    const float* mixer_w   = (const float*)d_in[4];
    const float* mixer_b   = (const float*)d_in[5];
    const float* enc_ln_w  = (const float*)d_in[6];
    const float* enc_ln_b  = (const float*)d_in[7];
    const float* in_proj_w = (const float*)d_in[8];
    const float* conv_w    = (const float*)d_in[9];
    const float* conv_b    = (const float*)d_in[10];
    const float* dt_bias   = (const float*)d_in[11];
    const float* A_log     = (const float*)d_in[12];
    const float* D_skip    = (const float*)d_in[13];
    const float* norm_w    = (const float*)d_in[14];
    const float* out_proj_w= (const float*)d_in[15];
    const float* ln_w      = (const float*)d_in[16];
    const float* ln_b      = (const float*)d_in[17];
    const float* h1w       = (const float*)d_in[18];
    const float* h1b       = (const float*)d_in[19];
    const float* h2w       = (const float*)d_in[20];
    const float* h2b       = (const float*)d_in[21];
    float* out = (float*)d_out;

    float *xsr, *mixw, *biasenc, *h, *zx, *y, *o;
    cudaGetSymbolAddress((void**)&xsr,     g_xsr);
    cudaGetSymbolAddress((void**)&mixw,    g_mixw);
    cudaGetSymbolAddress((void**)&biasenc, g_biasenc);
    cudaGetSymbolAddress((void**)&h,       g_h);
    cudaGetSymbolAddress((void**)&zx,      g_zx);
    cudaGetSymbolAddress((void**)&y,       g_y);
    cudaGetSymbolAddress((void**)&o,       g_o);

    // encoder
    k_sconv<<<dim3(KPAD, BB), NT>>>(x, sconv_w, sconv_b);
    k_mixprep<<<(DM * KPAD + 255) / 256, 256>>>(mixer_w);
    k_biasenc<<<1, DM>>>(emb, mixer_b);
    sgemm_nt<<<dim3(2, TOK / 128), 256>>>(xsr, mixw, biasenc, h, TOK, DM, KPAD);
    k_ln<<<TOK, DM>>>(h, nullptr, enc_ln_w, enc_ln_b, h);

    // mamba2 layers
    for (int l = 0; l < NL; l++) {
        sgemm_nt<<<dim3((DPROJ + 127) / 128, TOK / 128), 256>>>(
            h, in_proj_w + (size_t)l * DPROJ * DM, nullptr, zx, TOK, DPROJ, DM);
        k_dt<<<(TOK * NH + 255) / 256, 256>>>(dt_bias + l * NH, A_log + l * NH);
        k_conv<<<(TOK * CONVD + 255) / 256, 256>>>(conv_w + (size_t)l * CONVD * 4,
                                                   conv_b + (size_t)l * CONVD);
        k_scan<<<dim3(BB, NH), 512>>>(D_skip + l * NH);
        k_rms<<<TOK, 256>>>(norm_w + (size_t)l * DI);
        sgemm_nt<<<dim3(2, TOK / 128), 256>>>(
            y, out_proj_w + (size_t)l * DM * DI, nullptr, o, TOK, DM, DI);
        k_ln<<<TOK, DM>>>(o, h, ln_w + l * DM, ln_b + l * DM, h);
    }

    // head
    k_pool<<<BB, DM>>>();
    k_head<<<BB, 128>>>(h1w, h1b, h2w, h2b, out);
}

// round 4
// speedup vs baseline: 2.0731x; 2.0731x over previous
#include <cuda_runtime.h>
#include <stdint.h>
#include <math.h>

#define BB     64
#define NCH    129
#define NT     200
#define DM     256
#define DSTATE 16
#define HD     32
#define NL     4
#define DI     512
#define NH     16
#define CONVD  544
#define DPROJ  1072
#define TOK    (BB*NT)   // 12800
#define KPAD   144       // 129 padded to mult of 16 (tf32 gemm needs K%16==0)
#define SMS    20        // smem row stride (16 + 4 pad) -> conflict-free frags

// ---------------- scratch (device globals; no allocation allowed) ----------
__device__ float g_xsr[TOK*KPAD];
__device__ float g_mixw[DM*KPAD];
__device__ float g_biasenc[DM];
__device__ float g_h[TOK*DM];
__device__ float g_zx[TOK*DPROJ];
__device__ float g_xbc[TOK*CONVD];
__device__ float g_dt[TOK*NH];
__device__ float g_dA[TOK*NH];
__device__ float g_y[TOK*DI];
__device__ float g_o[TOK*DM];
__device__ float g_pool[BB*DM];

// ---------------- helpers --------------------------------------------------
__device__ __forceinline__ float blockReduceSum(float v, volatile float* sh) {
    __syncthreads();
    int lane = threadIdx.x & 31, wid = threadIdx.x >> 5;
#pragma unroll
    for (int o = 16; o > 0; o >>= 1) v += __shfl_xor_sync(0xffffffffu, v, o);
    if (lane == 0) sh[wid] = v;
    __syncthreads();
    float tot = 0.f;
    int nw = blockDim.x >> 5;
    for (int i = 0; i < nw; i++) tot += sh[i];
    return tot;
}

__device__ __forceinline__ float siluf(float x) { return x / (1.f + expf(-x)); }

__device__ __forceinline__ uint32_t f2tf(float x) {
    uint32_t r; asm("cvt.rna.tf32.f32 %0, %1;" : "=r"(r) : "f"(x)); return r;
}
__device__ __forceinline__ void mma_tf32(float* c, const uint32_t* a, const uint32_t* b) {
    asm volatile("mma.sync.aligned.m16n8k8.row.col.f32.tf32.tf32.f32 "
        "{%0,%1,%2,%3}, {%4,%5,%6,%7}, {%8,%9}, {%0,%1,%2,%3};"
        : "+f"(c[0]), "+f"(c[1]), "+f"(c[2]), "+f"(c[3])
        : "r"(a[0]), "r"(a[1]), "r"(a[2]), "r"(a[3]), "r"(b[0]), "r"(b[1]));
}
__device__ __forceinline__ void cpa16(uint32_t dst, const void* src, int sz) {
    asm volatile("cp.async.ca.shared.global [%0], [%1], 16, %2;"
                 :: "r"(dst), "l"(src), "r"(sz));
}

// ---------------- TF32 tensor-core GEMM ------------------------------------
// C[m,n] = sum_k A[m,k] * W[n,k] (+ bias[n]); A: MxK, W: NxK row-major.
// M%128==0, K%16==0. N arbitrary (zfill + store guards).
__global__ void __launch_bounds__(256, 2)
gemm_tf32(const float* __restrict__ A, const float* __restrict__ W,
          const float* __restrict__ bias, float* __restrict__ C,
          int M, int N, int K) {
    __shared__ float As[2][128 * SMS];
    __shared__ float Bs[2][128 * SMS];
    const int bm = blockIdx.y * 128, bn = blockIdx.x * 128;
    const int tid = threadIdx.x, lane = tid & 31, warp = tid >> 5;
    const int wm = (warp & 1) * 64, wn = (warp >> 1) * 32;
    const int r0 = lane >> 2, c0 = lane & 3;

    float acc[4][4][4];
#pragma unroll
    for (int i = 0; i < 4; i++)
#pragma unroll
        for (int j = 0; j < 4; j++)
#pragma unroll
            for (int k = 0; k < 4; k++) acc[i][j][k] = 0.f;

    // loader: thread does rows lr, lr+64; 16B per row per buffer
    const int lr = tid >> 2, lc = (tid & 3) * 4;
    const float* Ap0 = A + (size_t)(bm + lr) * K + lc;
    const float* Ap1 = A + (size_t)(bm + lr + 64) * K + lc;
    const int bnr0 = bn + lr, bnr1 = bn + lr + 64;
    const float* Bp0 = W + (size_t)(bnr0 < N ? bnr0 : 0) * K + lc;
    const float* Bp1 = W + (size_t)(bnr1 < N ? bnr1 : 0) * K + lc;
    const int szb0 = bnr0 < N ? 16 : 0, szb1 = bnr1 < N ? 16 : 0;

    uint32_t aAs[2], aBs[2];
    aAs[0] = (uint32_t)__cvta_generic_to_shared(&As[0][0]);
    aAs[1] = (uint32_t)__cvta_generic_to_shared(&As[1][0]);
    aBs[0] = (uint32_t)__cvta_generic_to_shared(&Bs[0][0]);
    aBs[1] = (uint32_t)__cvta_generic_to_shared(&Bs[1][0]);
    const uint32_t dof0 = (uint32_t)(lr * SMS + lc) * 4u;
    const uint32_t dof1 = (uint32_t)((lr + 64) * SMS + lc) * 4u;

    const int KT = K >> 4;

#define LOADT(kt, buf)                                                \
    do {                                                              \
        int ko = (kt) * 16;                                           \
        cpa16(aAs[buf] + dof0, Ap0 + ko, 16);                         \
        cpa16(aAs[buf] + dof1, Ap1 + ko, 16);                         \
        cpa16(aBs[buf] + dof0, Bp0 + ko, szb0);                       \
        cpa16(aBs[buf] + dof1, Bp1 + ko, szb1);                       \
        asm volatile("cp.async.commit_group;");                       \
    } while (0)

    LOADT(0, 0);
    for (int kt = 0; kt < KT; kt++) {
        asm volatile("cp.async.wait_group 0;");
        __syncthreads();
        if (kt + 1 < KT) LOADT(kt + 1, (kt + 1) & 1);
        const int buf = kt & 1;
#pragma unroll
        for (int ks = 0; ks < 2; ks++) {
            uint32_t af[4][4], bf[4][2];
#pragma unroll
            for (int mi = 0; mi < 4; mi++) {
                const float* p = &As[buf][(wm + mi * 16 + r0) * SMS + ks * 8 + c0];
                af[mi][0] = f2tf(p[0]);
                af[mi][1] = f2tf(p[8 * SMS]);
                af[mi][2] = f2tf(p[4]);
                af[mi][3] = f2tf(p[8 * SMS + 4]);
            }
#pragma unroll
            for (int nj = 0; nj < 4; nj++) {
                const float* p = &Bs[buf][(wn + nj * 8 + r0) * SMS + ks * 8 + c0];
                bf[nj][0] = f2tf(p[0]);
                bf[nj][1] = f2tf(p[4]);
            }
#pragma unroll
            for (int mi = 0; mi < 4; mi++)
#pragma unroll
                for (int nj = 0; nj < 4; nj++)
                    mma_tf32(acc[mi][nj], af[mi], bf[nj]);
        }
    }
#undef LOADT

    // epilogue
#pragma unroll
    for (int mi = 0; mi < 4; mi++) {
        int row = bm + wm + mi * 16 + r0;
#pragma unroll
        for (int nj = 0; nj < 4; nj++) {
            int col = bn + wn + nj * 8 + c0 * 2;
            if (col < N) {
                float b0 = 0.f, b1 = 0.f;
                if (bias != nullptr) { b0 = bias[col]; b1 = bias[col + 1]; }
                float2 v0 = make_float2(acc[mi][nj][0] + b0, acc[mi][nj][1] + b1);
                float2 v1 = make_float2(acc[mi][nj][2] + b0, acc[mi][nj][3] + b1);
                *(float2*)&C[(size_t)row * N + col] = v0;
                *(float2*)&C[(size_t)(row + 8) * N + col] = v1;
            }
        }
    }
}

// ---------------- encoder --------------------------------------------------
__global__ void k_sconv(const float* __restrict__ x, const float* __restrict__ w,
                        const float* __restrict__ bias) {
    int c = blockIdx.x, b = blockIdx.y, t = threadIdx.x; // c in [0,KPAD)
    float v = 0.f;
    if (c < NCH) {
        const float* xr = x + (size_t)(b * NCH + c) * NT;
        float w0 = w[c * 3], w1 = w[c * 3 + 1], w2 = w[c * 3 + 2];
        float xm = (t > 0) ? xr[t - 1] : 0.f;
        float x0 = xr[t];
        float xp = (t < NT - 1) ? xr[t + 1] : 0.f;
        v = xm * w0 + x0 * w1 + xp * w2 + bias[c];
    }
    g_xsr[(size_t)(b * NT + t) * KPAD + c] = v;
}

__global__ void k_mixprep(const float* __restrict__ mw) {
    int idx = blockIdx.x * blockDim.x + threadIdx.x;
    if (idx >= DM * KPAD) return;
    int d = idx / KPAD, k = idx % KPAD;
    g_mixw[idx] = (k < NCH) ? mw[d * NCH + k] : 0.f;
}

__global__ void k_biasenc(const float* __restrict__ emb, const float* __restrict__ mb) {
    int d = threadIdx.x;
    float s = 0.f;
    for (int c = 0; c < NCH; c++) s += emb[c * DM + d];
    g_biasenc[d] = mb[d] + s * (1.f / NCH);
}

// ---------------- layernorm ------------------------------------------------
__global__ void k_ln(const float* __restrict__ in, const float* __restrict__ res,
                     const float* __restrict__ w, const float* __restrict__ b,
                     float* __restrict__ out) {
    __shared__ float sh[8];
    int row = blockIdx.x, tid = threadIdx.x;
    float v = in[(size_t)row * DM + tid];
    if (res != nullptr) v += res[(size_t)row * DM + tid];
    float mean = blockReduceSum(v, sh) * (1.f / DM);
    float d = v - mean;
    float var = blockReduceSum(d * d, sh) * (1.f / DM);
    out[(size_t)row * DM + tid] = d * rsqrtf(var + 1e-5f) * w[tid] + b[tid];
}

// ---------------- per-layer pieces -----------------------------------------
__global__ void k_dt(const float* __restrict__ dtb, const float* __restrict__ alog) {
    int idx = blockIdx.x * blockDim.x + threadIdx.x;
    if (idx >= TOK * NH) return;
    int h = idx & 15, bt = idx >> 4;
    float raw = g_zx[(size_t)bt * DPROJ + DI + CONVD + h] + dtb[h];
    float d = raw > 20.f ? raw : log1pf(expf(raw));
    g_dt[idx] = d;
    g_dA[idx] = expf(-d * expf(alog[h]));
}

__global__ void k_conv(const float* __restrict__ cw, const float* __restrict__ cb) {
    int idx = blockIdx.x * blockDim.x + threadIdx.x;
    if (idx >= TOK * CONVD) return;
    int c = idx % CONVD;
    int bt = idx / CONVD;
    int t = bt % NT, b = bt / NT;
    float acc = cb[c];
    const float* wr = cw + c * 4;
#pragma unroll
    for (int k = 0; k < 4; k++) {
        int tt = t - 3 + k;
        if (tt >= 0) acc = fmaf(g_zx[(size_t)(b * NT + tt) * DPROJ + DI + c], wr[k], acc);
    }
    g_xbc[idx] = siluf(acc);
}

// register-state SSM scan; block=(b, p-half); thread=(h, p); 16 states/thread
__global__ void k_scan2(const float* __restrict__ Dsk) {
    int b = blockIdx.x, half = blockIdx.y;
    int tid = threadIdx.x;                    // 256
    int h = tid >> 4, p = (tid & 15) + half * 16;
    __shared__ float sBC[2][32];              // B[0:16], C[16:32]
    __shared__ float sDa[2][16], sDt[2][16];

    float st[DSTATE];
#pragma unroll
    for (int n = 0; n < DSTATE; n++) st[n] = 0.f;
    float Dh = Dsk[h];
    const int base = b * NT;
    const float* row0 = g_xbc + (size_t)base * CONVD;

    if (tid < 32)       sBC[0][tid] = row0[DI + tid];
    else if (tid < 48)  sDa[0][tid - 32] = g_dA[base * NH + tid - 32];
    else if (tid < 64)  sDt[0][tid - 48] = g_dt[base * NH + tid - 48];
    float xp = row0[h * HD + p];
    __syncthreads();

    for (int t = 0; t < NT; t++) {
        const int buf = t & 1, nb = buf ^ 1;
        const int bt = base + t;
        // prefetch t+1 into regs (overlaps compute)
        float stg = 0.f, xpn = 0.f;
        if (t + 1 < NT) {
            const float* row = g_xbc + (size_t)(bt + 1) * CONVD;
            if (tid < 32)      stg = row[DI + tid];
            else if (tid < 48) stg = g_dA[(bt + 1) * NH + tid - 32];
            else if (tid < 64) stg = g_dt[(bt + 1) * NH + tid - 48];
            xpn = row[h * HD + p];
        }
        float dAh = sDa[buf][h], dth = sDt[buf][h];
        float dtx = dth * xp;
        float a0 = 0.f, a1 = 0.f;
#pragma unroll
        for (int n = 0; n < DSTATE; n += 2) {
            st[n]     = fmaf(dAh, st[n],     dtx * sBC[buf][n]);
            st[n + 1] = fmaf(dAh, st[n + 1], dtx * sBC[buf][n + 1]);
            a0 = fmaf(st[n],     sBC[buf][16 + n],     a0);
            a1 = fmaf(st[n + 1], sBC[buf][16 + n + 1], a1);
        }
        g_y[(size_t)bt * DI + h * HD + p] = a0 + a1 + xp * Dh;
        if (t + 1 < NT) {
            if (tid < 32)      sBC[nb][tid] = stg;
            else if (tid < 48) sDa[nb][tid - 32] = stg;
            else if (tid < 64) sDt[nb][tid - 48] = stg;
        }
        xp = xpn;
        __syncthreads();
    }
}

// gated RMSNorm over 512, in place on g_y
__global__ void k_rms(const float* __restrict__ nw) {
    __shared__ float sh[8];
    int row = blockIdx.x, tid = threadIdx.x; // 256
    float z0 = g_zx[(size_t)row * DPROJ + tid];
    float z1 = g_zx[(size_t)row * DPROJ + 256 + tid];
    float y0 = g_y[(size_t)row * DI + tid];
    float y1 = g_y[(size_t)row * DI + 256 + tid];
    y0 *= siluf(z0);
    y1 *= siluf(z1);
    float ss = blockReduceSum(y0 * y0 + y1 * y1, sh);
    float sc = rsqrtf(ss * (1.f / DI) + 1e-5f);
    g_y[(size_t)row * DI + tid]       = y0 * sc * nw[tid];
    g_y[(size_t)row * DI + 256 + tid] = y1 * sc * nw[256 + tid];
}

// ---------------- head -----------------------------------------------------
__global__ void k_pool() {
    int b = blockIdx.x, d = threadIdx.x;
    float s = 0.f;
    for (int t = 0; t < NT; t++) s += g_h[(size_t)(b * NT + t) * DM + d];
    g_pool[b * DM + d] = s * (1.f / NT);
}

__global__ void k_head(const float* __restrict__ w1, const float* __restrict__ b1,
                       const float* __restrict__ w2, const float* __restrict__ b2,
                       float* __restrict__ out) {
    __shared__ float sp[DM];
    __shared__ float sh[4];
    int b = blockIdx.x, j = threadIdx.x;    // 128
    sp[j] = g_pool[b * DM + j];
    sp[j + 128] = g_pool[b * DM + 128 + j];
    __syncthreads();
    float acc = b1[j];
    const float* wr = w1 + j * DM;
#pragma unroll 8
    for (int k = 0; k < DM; k++) acc = fmaf(sp[k], wr[k], acc);
    float r = fmaxf(acc, 0.f) * w2[j];
#pragma unroll
    for (int o = 16; o > 0; o >>= 1) r += __shfl_xor_sync(0xffffffffu, r, o);
    int lane = j & 31, wid = j >> 5;
    if (lane == 0) sh[wid] = r;
    __syncthreads();
    if (j == 0) out[b] = sh[0] + sh[1] + sh[2] + sh[3] + b2[0];
}

// ---------------- launch ----------------------------------------------------
extern "C" void kernel_launch(void* const* d_in, const int* in_sizes, int n_in,
                              void* d_out, int out_size) {
    const float* x         = (const float*)d_in[0];
    const float* emb       = (const float*)d_in[1];
    const float* sconv_w   = (const float*)d_in[2];
    const float* sconv_b   = (const float*)d_in[3];
    const float* mixer_w   = (const float*)d_in[4];
    const float* mixer_b   = (const float*)d_in[5];
    const float* enc_ln_w  = (const float*)d_in[6];
    const float* enc_ln_b  = (const float*)d_in[7];
    const float* in_proj_w = (const float*)d_in[8];
    const float* conv_w    = (const float*)d_in[9];
    const float* conv_b    = (const float*)d_in[10];
    const float* dt_bias   = (const float*)d_in[11];
    const float* A_log     = (const float*)d_in[12];
    const float* D_skip    = (const float*)d_in[13];
    const float* norm_w    = (const float*)d_in[14];
    const float* out_proj_w= (const float*)d_in[15];
    const float* ln_w      = (const float*)d_in[16];
    const float* ln_b      = (const float*)d_in[17];
    const float* h1w       = (const float*)d_in[18];
    const float* h1b       = (const float*)d_in[19];
    const float* h2w       = (const float*)d_in[20];
    const float* h2b       = (const float*)d_in[21];
    float* out = (float*)d_out;

    float *xsr, *mixw, *biasenc, *h, *zx, *y, *o;
    cudaGetSymbolAddress((void**)&xsr,     g_xsr);
    cudaGetSymbolAddress((void**)&mixw,    g_mixw);
    cudaGetSymbolAddress((void**)&biasenc, g_biasenc);
    cudaGetSymbolAddress((void**)&h,       g_h);
    cudaGetSymbolAddress((void**)&zx,      g_zx);
    cudaGetSymbolAddress((void**)&y,       g_y);
    cudaGetSymbolAddress((void**)&o,       g_o);

    // encoder
    k_sconv<<<dim3(KPAD, BB), NT>>>(x, sconv_w, sconv_b);
    k_mixprep<<<(DM * KPAD + 255) / 256, 256>>>(mixer_w);
    k_biasenc<<<1, DM>>>(emb, mixer_b);
    gemm_tf32<<<dim3(2, TOK / 128), 256>>>(xsr, mixw, biasenc, h, TOK, DM, KPAD);
    k_ln<<<TOK, DM>>>(h, nullptr, enc_ln_w, enc_ln_b, h);

    // mamba2 layers
    for (int l = 0; l < NL; l++) {
        gemm_tf32<<<dim3((DPROJ + 127) / 128, TOK / 128), 256>>>(
            h, in_proj_w + (size_t)l * DPROJ * DM, nullptr, zx, TOK, DPROJ, DM);
        k_dt<<<(TOK * NH + 255) / 256, 256>>>(dt_bias + l * NH, A_log + l * NH);
        k_conv<<<(TOK * CONVD + 255) / 256, 256>>>(conv_w + (size_t)l * CONVD * 4,
                                                   conv_b + (size_t)l * CONVD);
        k_scan2<<<dim3(BB, 2), 256>>>(D_skip + l * NH);
        k_rms<<<TOK, 256>>>(norm_w + (size_t)l * DI);
        gemm_tf32<<<dim3(2, TOK / 128), 256>>>(
            y, out_proj_w + (size_t)l * DM * DI, nullptr, o, TOK, DM, DI);
        k_ln<<<TOK, DM>>>(o, h, ln_w + l * DM, ln_b + l * DM, h);
    }

    // head
    k_pool<<<BB, DM>>>();
    k_head<<<BB, 128>>>(h1w, h1b, h2w, h2b, out);
}

// round 5
// speedup vs baseline: 2.6777x; 1.2916x over previous
#include <cuda_runtime.h>
#include <stdint.h>
#include <math.h>

#define BB     64
#define NCH    129
#define NT     200
#define DM     256
#define DSTATE 16
#define HD     32
#define NL     4
#define DI     512
#define NH     16
#define CONVD  544
#define DPROJ  1072
#define TOK    (BB*NT)   // 12800
#define KPAD   144
#define SMS    20
#define TTILE  20        // scan time-tile (NT % TTILE == 0)

// ---------------- scratch (device globals; no allocation allowed) ----------
__device__ float g_xsr[TOK*KPAD];
__device__ float g_mixw[DM*KPAD];
__device__ float g_biasenc[DM];
__device__ float g_h[TOK*DM];
__device__ float g_zx[TOK*DPROJ];
__device__ float g_xbc[TOK*CONVD];
__device__ float g_dt[TOK*NH];
__device__ float g_dA[TOK*NH];
__device__ float g_y[TOK*DI];
__device__ float g_o[TOK*DM];
__device__ float g_pool[BB*DM];

// ---------------- helpers --------------------------------------------------
__device__ __forceinline__ float blockReduceSum(float v, volatile float* sh) {
    __syncthreads();
    int lane = threadIdx.x & 31, wid = threadIdx.x >> 5;
#pragma unroll
    for (int o = 16; o > 0; o >>= 1) v += __shfl_xor_sync(0xffffffffu, v, o);
    if (lane == 0) sh[wid] = v;
    __syncthreads();
    float tot = 0.f;
    int nw = blockDim.x >> 5;
    for (int i = 0; i < nw; i++) tot += sh[i];
    return tot;
}

__device__ __forceinline__ float siluf(float x) { return x / (1.f + expf(-x)); }

__device__ __forceinline__ uint32_t f2tf(float x) {
    uint32_t r; asm("cvt.rna.tf32.f32 %0, %1;" : "=r"(r) : "f"(x)); return r;
}
__device__ __forceinline__ void mma_tf32(float* c, const uint32_t* a, const uint32_t* b) {
    asm volatile("mma.sync.aligned.m16n8k8.row.col.f32.tf32.tf32.f32 "
        "{%0,%1,%2,%3}, {%4,%5,%6,%7}, {%8,%9}, {%0,%1,%2,%3};"
        : "+f"(c[0]), "+f"(c[1]), "+f"(c[2]), "+f"(c[3])
        : "r"(a[0]), "r"(a[1]), "r"(a[2]), "r"(a[3]), "r"(b[0]), "r"(b[1]));
}
__device__ __forceinline__ void cpa16(uint32_t dst, const void* src, int sz) {
    asm volatile("cp.async.ca.shared.global [%0], [%1], 16, %2;"
                 :: "r"(dst), "l"(src), "r"(sz));
}

// ---------------- TF32 tensor-core GEMM (unchanged from R4) -----------------
__global__ void __launch_bounds__(256, 2)
gemm_tf32(const float* __restrict__ A, const float* __restrict__ W,
          const float* __restrict__ bias, float* __restrict__ C,
          int M, int N, int K) {
    __shared__ float As[2][128 * SMS];
    __shared__ float Bs[2][128 * SMS];
    const int bm = blockIdx.y * 128, bn = blockIdx.x * 128;
    const int tid = threadIdx.x, lane = tid & 31, warp = tid >> 5;
    const int wm = (warp & 1) * 64, wn = (warp >> 1) * 32;
    const int r0 = lane >> 2, c0 = lane & 3;

    float acc[4][4][4];
#pragma unroll
    for (int i = 0; i < 4; i++)
#pragma unroll
        for (int j = 0; j < 4; j++)
#pragma unroll
            for (int k = 0; k < 4; k++) acc[i][j][k] = 0.f;

    const int lr = tid >> 2, lc = (tid & 3) * 4;
    const float* Ap0 = A + (size_t)(bm + lr) * K + lc;
    const float* Ap1 = A + (size_t)(bm + lr + 64) * K + lc;
    const int bnr0 = bn + lr, bnr1 = bn + lr + 64;
    const float* Bp0 = W + (size_t)(bnr0 < N ? bnr0 : 0) * K + lc;
    const float* Bp1 = W + (size_t)(bnr1 < N ? bnr1 : 0) * K + lc;
    const int szb0 = bnr0 < N ? 16 : 0, szb1 = bnr1 < N ? 16 : 0;

    uint32_t aAs[2], aBs[2];
    aAs[0] = (uint32_t)__cvta_generic_to_shared(&As[0][0]);
    aAs[1] = (uint32_t)__cvta_generic_to_shared(&As[1][0]);
    aBs[0] = (uint32_t)__cvta_generic_to_shared(&Bs[0][0]);
    aBs[1] = (uint32_t)__cvta_generic_to_shared(&Bs[1][0]);
    const uint32_t dof0 = (uint32_t)(lr * SMS + lc) * 4u;
    const uint32_t dof1 = (uint32_t)((lr + 64) * SMS + lc) * 4u;

    const int KT = K >> 4;

#define LOADT(kt, buf)                                                \
    do {                                                              \
        int ko = (kt) * 16;                                           \
        cpa16(aAs[buf] + dof0, Ap0 + ko, 16);                         \
        cpa16(aAs[buf] + dof1, Ap1 + ko, 16);                         \
        cpa16(aBs[buf] + dof0, Bp0 + ko, szb0);                       \
        cpa16(aBs[buf] + dof1, Bp1 + ko, szb1);                       \
        asm volatile("cp.async.commit_group;");                       \
    } while (0)

    LOADT(0, 0);
    for (int kt = 0; kt < KT; kt++) {
        asm volatile("cp.async.wait_group 0;");
        __syncthreads();
        if (kt + 1 < KT) LOADT(kt + 1, (kt + 1) & 1);
        const int buf = kt & 1;
#pragma unroll
        for (int ks = 0; ks < 2; ks++) {
            uint32_t af[4][4], bf[4][2];
#pragma unroll
            for (int mi = 0; mi < 4; mi++) {
                const float* p = &As[buf][(wm + mi * 16 + r0) * SMS + ks * 8 + c0];
                af[mi][0] = f2tf(p[0]);
                af[mi][1] = f2tf(p[8 * SMS]);
                af[mi][2] = f2tf(p[4]);
                af[mi][3] = f2tf(p[8 * SMS + 4]);
            }
#pragma unroll
            for (int nj = 0; nj < 4; nj++) {
                const float* p = &Bs[buf][(wn + nj * 8 + r0) * SMS + ks * 8 + c0];
                bf[nj][0] = f2tf(p[0]);
                bf[nj][1] = f2tf(p[4]);
            }
#pragma unroll
            for (int mi = 0; mi < 4; mi++)
#pragma unroll
                for (int nj = 0; nj < 4; nj++)
                    mma_tf32(acc[mi][nj], af[mi], bf[nj]);
        }
    }
#undef LOADT

#pragma unroll
    for (int mi = 0; mi < 4; mi++) {
        int row = bm + wm + mi * 16 + r0;
#pragma unroll
        for (int nj = 0; nj < 4; nj++) {
            int col = bn + wn + nj * 8 + c0 * 2;
            if (col < N) {
                float b0 = 0.f, b1 = 0.f;
                if (bias != nullptr) { b0 = bias[col]; b1 = bias[col + 1]; }
                float2 v0 = make_float2(acc[mi][nj][0] + b0, acc[mi][nj][1] + b1);
                float2 v1 = make_float2(acc[mi][nj][2] + b0, acc[mi][nj][3] + b1);
                *(float2*)&C[(size_t)row * N + col] = v0;
                *(float2*)&C[(size_t)(row + 8) * N + col] = v1;
            }
        }
    }
}

// ---------------- encoder --------------------------------------------------
__global__ void k_sconv(const float* __restrict__ x, const float* __restrict__ w,
                        const float* __restrict__ bias) {
    int c = blockIdx.x, b = blockIdx.y, t = threadIdx.x;
    float v = 0.f;
    if (c < NCH) {
        const float* xr = x + (size_t)(b * NCH + c) * NT;
        float w0 = w[c * 3], w1 = w[c * 3 + 1], w2 = w[c * 3 + 2];
        float xm = (t > 0) ? xr[t - 1] : 0.f;
        float x0 = xr[t];
        float xp = (t < NT - 1) ? xr[t + 1] : 0.f;
        v = xm * w0 + x0 * w1 + xp * w2 + bias[c];
    }
    g_xsr[(size_t)(b * NT + t) * KPAD + c] = v;
}

__global__ void k_mixprep(const float* __restrict__ mw) {
    int idx = blockIdx.x * blockDim.x + threadIdx.x;
    if (idx >= DM * KPAD) return;
    int d = idx / KPAD, k = idx % KPAD;
    g_mixw[idx] = (k < NCH) ? mw[d * NCH + k] : 0.f;
}

__global__ void k_biasenc(const float* __restrict__ emb, const float* __restrict__ mb) {
    int d = threadIdx.x;
    float s = 0.f;
    for (int c = 0; c < NCH; c++) s += emb[c * DM + d];
    g_biasenc[d] = mb[d] + s * (1.f / NCH);
}

// ---------------- layernorm ------------------------------------------------
__global__ void k_ln(const float* __restrict__ in, const float* __restrict__ res,
                     const float* __restrict__ w, const float* __restrict__ b,
                     float* __restrict__ out) {
    __shared__ float sh[8];
    int row = blockIdx.x, tid = threadIdx.x;
    float v = in[(size_t)row * DM + tid];
    if (res != nullptr) v += res[(size_t)row * DM + tid];
    float mean = blockReduceSum(v, sh) * (1.f / DM);
    float d = v - mean;
    float var = blockReduceSum(d * d, sh) * (1.f / DM);
    out[(size_t)row * DM + tid] = d * rsqrtf(var + 1e-5f) * w[tid] + b[tid];
}

// ---------------- per-layer pieces -----------------------------------------
__global__ void k_dt(const float* __restrict__ dtb, const float* __restrict__ alog) {
    int idx = blockIdx.x * blockDim.x + threadIdx.x;
    if (idx >= TOK * NH) return;
    int h = idx & 15, bt = idx >> 4;
    float raw = g_zx[(size_t)bt * DPROJ + DI + CONVD + h] + dtb[h];
    float d = raw > 20.f ? raw : log1pf(expf(raw));
    g_dt[idx] = d;
    g_dA[idx] = expf(-d * expf(alog[h]));
}

__global__ void k_conv(const float* __restrict__ cw, const float* __restrict__ cb) {
    int idx = blockIdx.x * blockDim.x + threadIdx.x;
    if (idx >= TOK * CONVD) return;
    int c = idx % CONVD;
    int bt = idx / CONVD;
    int t = bt % NT, b = bt / NT;
    float acc = cb[c];
    const float* wr = cw + c * 4;
#pragma unroll
    for (int k = 0; k < 4; k++) {
        int tt = t - 3 + k;
        if (tt >= 0) acc = fmaf(g_zx[(size_t)(b * NT + tt) * DPROJ + DI + c], wr[k], acc);
    }
    g_xbc[idx] = siluf(acc);
}

// -------- time-tiled SSM scan: block=(b, p-half); thread=(h, p) ------------
// 16 states/thread in regs; B/C/dA/dt staged per 20-step tile in smem;
// x prefetched into regs per tile (MLP=20); 2 syncs per tile, not per step.
__global__ void k_scan3(const float* __restrict__ Dsk) {
    const int b = blockIdx.x, half = blockIdx.y;
    const int tid = threadIdx.x;                // 256
    const int h = tid >> 4, p = (tid & 15) + half * 16;
    __shared__ float sB[TTILE][16], sC[TTILE][16];
    __shared__ float sA[TTILE][16], sT[TTILE][16];

    float st[DSTATE];
#pragma unroll
    for (int n = 0; n < DSTATE; n++) st[n] = 0.f;
    const float Dh = Dsk[h];
    const int base = b * NT;
    const size_t xoff = (size_t)h * HD + p;

    for (int t0 = 0; t0 < NT; t0 += TTILE) {
        // prefetch this tile's x values (independent loads, latency-overlapped)
        float xv[TTILE];
#pragma unroll
        for (int tl = 0; tl < TTILE; tl++)
            xv[tl] = __ldg(g_xbc + (size_t)(base + t0 + tl) * CONVD + xoff);

        __syncthreads();   // previous tile fully consumed
        // cooperative stage of B/C/dA/dt: 20*64 values, 5 per thread
#pragma unroll
        for (int i = tid; i < TTILE * 64; i += 256) {
            const int tl = i >> 6, j = i & 63;
            const int bt = base + t0 + tl;
            if (j < 32) {
                float v = g_xbc[(size_t)bt * CONVD + DI + j];
                if (j < 16) sB[tl][j] = v; else sC[tl][j - 16] = v;
            } else if (j < 48) {
                sA[tl][j - 32] = g_dA[bt * NH + (j - 32)];
            } else {
                sT[tl][j - 48] = g_dt[bt * NH + (j - 48)];
            }
        }
        __syncthreads();

#pragma unroll
        for (int tl = 0; tl < TTILE; tl++) {
            const float xp = xv[tl];
            const float dAh = sA[tl][h];
            const float dtx = sT[tl][h] * xp;
            float a0 = 0.f, a1 = 0.f;
#pragma unroll
            for (int n = 0; n < DSTATE; n += 2) {
                st[n]     = fmaf(dAh, st[n],     dtx * sB[tl][n]);
                st[n + 1] = fmaf(dAh, st[n + 1], dtx * sB[tl][n + 1]);
                a0 = fmaf(st[n],     sC[tl][n],     a0);
                a1 = fmaf(st[n + 1], sC[tl][n + 1], a1);
            }
            g_y[(size_t)(base + t0 + tl) * DI + xoff] = a0 + a1 + xp * Dh;
        }
    }
}

// gated RMSNorm over 512, in place on g_y
__global__ void k_rms(const float* __restrict__ nw) {
    __shared__ float sh[8];
    int row = blockIdx.x, tid = threadIdx.x;
    float z0 = g_zx[(size_t)row * DPROJ + tid];
    float z1 = g_zx[(size_t)row * DPROJ + 256 + tid];
    float y0 = g_y[(size_t)row * DI + tid];
    float y1 = g_y[(size_t)row * DI + 256 + tid];
    y0 *= siluf(z0);
    y1 *= siluf(z1);
    float ss = blockReduceSum(y0 * y0 + y1 * y1, sh);
    float sc = rsqrtf(ss * (1.f / DI) + 1e-5f);
    g_y[(size_t)row * DI + tid]       = y0 * sc * nw[tid];
    g_y[(size_t)row * DI + 256 + tid] = y1 * sc * nw[256 + tid];
}

// ---------------- head -----------------------------------------------------
__global__ void k_pool() {
    int b = blockIdx.x, d = threadIdx.x;
    float s = 0.f;
    for (int t = 0; t < NT; t++) s += g_h[(size_t)(b * NT + t) * DM + d];
    g_pool[b * DM + d] = s * (1.f / NT);
}

__global__ void k_head(const float* __restrict__ w1, const float* __restrict__ b1,
                       const float* __restrict__ w2, const float* __restrict__ b2,
                       float* __restrict__ out) {
    __shared__ float sp[DM];
    __shared__ float sh[4];
    int b = blockIdx.x, j = threadIdx.x;
    sp[j] = g_pool[b * DM + j];
    sp[j + 128] = g_pool[b * DM + 128 + j];
    __syncthreads();
    float acc = b1[j];
    const float* wr = w1 + j * DM;
#pragma unroll 8
    for (int k = 0; k < DM; k++) acc = fmaf(sp[k], wr[k], acc);
    float r = fmaxf(acc, 0.f) * w2[j];
#pragma unroll
    for (int o = 16; o > 0; o >>= 1) r += __shfl_xor_sync(0xffffffffu, r, o);
    int lane = j & 31, wid = j >> 5;
    if (lane == 0) sh[wid] = r;
    __syncthreads();
    if (j == 0) out[b] = sh[0] + sh[1] + sh[2] + sh[3] + b2[0];
}

// ---------------- launch ----------------------------------------------------
extern "C" void kernel_launch(void* const* d_in, const int* in_sizes, int n_in,
                              void* d_out, int out_size) {
    const float* x         = (const float*)d_in[0];
    const float* emb       = (const float*)d_in[1];
    const float* sconv_w   = (const float*)d_in[2];
    const float* sconv_b   = (const float*)d_in[3];
    const float* mixer_w   = (const float*)d_in[4];
    const float* mixer_b   = (const float*)d_in[5];
    const float* enc_ln_w  = (const float*)d_in[6];
    const float* enc_ln_b  = (const float*)d_in[7];
    const float* in_proj_w = (const float*)d_in[8];
    const float* conv_w    = (const float*)d_in[9];
    const float* conv_b    = (const float*)d_in[10];
    const float* dt_bias   = (const float*)d_in[11];
    const float* A_log     = (const float*)d_in[12];
    const float* D_skip    = (const float*)d_in[13];
    const float* norm_w    = (const float*)d_in[14];
    const float* out_proj_w= (const float*)d_in[15];
    const float* ln_w      = (const float*)d_in[16];
    const float* ln_b      = (const float*)d_in[17];
    const float* h1w       = (const float*)d_in[18];
    const float* h1b       = (const float*)d_in[19];
    const float* h2w       = (const float*)d_in[20];
    const float* h2b       = (const float*)d_in[21];
    float* out = (float*)d_out;

    float *xsr, *mixw, *biasenc, *h, *zx, *y, *o;
    cudaGetSymbolAddress((void**)&xsr,     g_xsr);
    cudaGetSymbolAddress((void**)&mixw,    g_mixw);
    cudaGetSymbolAddress((void**)&biasenc, g_biasenc);
    cudaGetSymbolAddress((void**)&h,       g_h);
    cudaGetSymbolAddress((void**)&zx,      g_zx);
    cudaGetSymbolAddress((void**)&y,       g_y);
    cudaGetSymbolAddress((void**)&o,       g_o);

    // encoder
    k_sconv<<<dim3(KPAD, BB), NT>>>(x, sconv_w, sconv_b);
    k_mixprep<<<(DM * KPAD + 255) / 256, 256>>>(mixer_w);
    k_biasenc<<<1, DM>>>(emb, mixer_b);
    gemm_tf32<<<dim3(2, TOK / 128), 256>>>(xsr, mixw, biasenc, h, TOK, DM, KPAD);
    k_ln<<<TOK, DM>>>(h, nullptr, enc_ln_w, enc_ln_b, h);

    // mamba2 layers
    for (int l = 0; l < NL; l++) {
        gemm_tf32<<<dim3((DPROJ + 127) / 128, TOK / 128), 256>>>(
            h, in_proj_w + (size_t)l * DPROJ * DM, nullptr, zx, TOK, DPROJ, DM);
        k_dt<<<(TOK * NH + 255) / 256, 256>>>(dt_bias + l * NH, A_log + l * NH);
        k_conv<<<(TOK * CONVD + 255) / 256, 256>>>(conv_w + (size_t)l * CONVD * 4,
                                                   conv_b + (size_t)l * CONVD);
        k_scan3<<<dim3(BB, 2), 256>>>(D_skip + l * NH);
        k_rms<<<TOK, 256>>>(norm_w + (size_t)l * DI);
        gemm_tf32<<<dim3(2, TOK / 128), 256>>>(
            y, out_proj_w + (size_t)l * DM * DI, nullptr, o, TOK, DM, DI);
        k_ln<<<TOK, DM>>>(o, h, ln_w + l * DM, ln_b + l * DM, h);
    }

    // head
    k_pool<<<BB, DM>>>();
    k_head<<<BB, 128>>>(h1w, h1b, h2w, h2b, out);
}